// round 1
// baseline (speedup 1.0000x reference)
#include <cuda_runtime.h>

#define Nn 1024
#define Hh 100
#define Gg 400
#define KE 125
#define Ll 40
#define EPSV 1e-20f

// ---------------- scratch (device globals; no allocation allowed) ----------------
__device__ float g_E[Nn * KE];     // embeddings [1024,125]
__device__ float g_P[Nn * Gg];     // precomputed input-projection gates [1024,400] (reused per layer)
__device__ float g_H0[Nn * Hh];    // layer0 hidden states
__device__ float g_H1[Nn * Hh];    // layer1 hidden states
__device__ float g_u[2 * Hh + 1];  // u1[100], u2[100], c0
__device__ float g_EA[Nn];
__device__ float g_EB[Nn];
__device__ float g_S;

// ---------------- helpers ----------------
__device__ __forceinline__ float sigf(float x) { return 1.f / (1.f + __expf(-x)); }
__device__ __forceinline__ float tanh_fast(float x) {
    x = fminf(fmaxf(x, -15.f), 15.f);
    float e = __expf(2.f * x);
    return (e - 1.f) / (e + 1.f);
}

// ---------------- K0: embedding gather ----------------
__global__ void gather_emb(const int* __restrict__ wi, const int* __restrict__ ti,
                           const float* __restrict__ wt, const float* __restrict__ tt) {
    int t = blockIdx.x;
    int w = wi[t];
    int g = ti[t];
    for (int j = threadIdx.x; j < KE; j += blockDim.x)
        g_E[t * KE + j] = (j < 100) ? wt[w * 100 + j] : tt[g * 25 + (j - 100)];
}

// ---------------- K1/K3: C[1024,400] = X[1024,K] @ W[400,K]^T + b1 + b2 ----------------
__global__ __launch_bounds__(256) void gemm_bias(const float* __restrict__ X,
                                                 const float* __restrict__ W,
                                                 const float* __restrict__ b1,
                                                 const float* __restrict__ b2,
                                                 float* __restrict__ C, int K) {
    __shared__ float Xs[64 * 127];  // rows of X tile, padded stride 127 (odd)
    __shared__ float Ws[32 * 127];  // rows of W tile
    int m0 = blockIdx.y * 64;
    int n0 = blockIdx.x * 32;
    int tid = threadIdx.x;

    for (int idx = tid; idx < 64 * K; idx += 256) {
        int r = idx / K, c = idx - r * K;
        Xs[r * 127 + c] = X[(m0 + r) * K + c];  // M=1024 divisible by 64, no guard
    }
    for (int idx = tid; idx < 32 * K; idx += 256) {
        int r = idx / K, c = idx - r * K;
        int n = n0 + r;
        Ws[r * 127 + c] = (n < Gg) ? W[n * K + c] : 0.f;
    }
    __syncthreads();

    int ty = tid >> 5, tx = tid & 31;
    float acc[8] = {0, 0, 0, 0, 0, 0, 0, 0};
    for (int k = 0; k < K; k++) {
        float wv = Ws[tx * 127 + k];  // stride 127: conflict-free
#pragma unroll
        for (int r = 0; r < 8; r++)
            acc[r] = fmaf(Xs[(ty + 8 * r) * 127 + k], wv, acc[r]);  // broadcast
    }
    int n = n0 + tx;
    if (n < Gg) {
        float bb = b1[n] + b2[n];
#pragma unroll
        for (int r = 0; r < 8; r++)
            C[(m0 + ty + 8 * r) * Gg + n] = acc[r] + bb;
    }
}

// ---------------- K2/K4: sequential LSTM recurrence (single CTA) ----------------
// P already contains x_t @ W_ih^T + b_ih + b_hh. Only h @ W_hh^T is on the chain.
__global__ __launch_bounds__(512, 1) void lstm_rec(const float* __restrict__ Whh,
                                                   const float* __restrict__ P,
                                                   float* __restrict__ Hout) {
    __shared__ __align__(16) float h_sh[Hh];
    __shared__ float g_sh[Gg];
    int tid = threadIdx.x;

    float w[100];
    if (tid < Gg) {
        const float4* Wr = reinterpret_cast<const float4*>(Whh + tid * Hh);  // 400B rows: 16B aligned
#pragma unroll
        for (int j = 0; j < 25; j++) {
            float4 v = Wr[j];
            w[4 * j] = v.x; w[4 * j + 1] = v.y; w[4 * j + 2] = v.z; w[4 * j + 3] = v.w;
        }
    }
    float c = 0.f;
    if (tid < Hh) h_sh[tid] = 0.f;
    __syncthreads();

    for (int t = 0; t < Nn; t++) {
        if (tid < Gg) {
            float p = P[t * Gg + tid];  // issued early, consumed after the dot (latency hidden)
            const float4* h4 = reinterpret_cast<const float4*>(h_sh);
            float a0 = 0.f, a1 = 0.f, a2 = 0.f, a3 = 0.f;
#pragma unroll
            for (int j = 0; j < 25; j++) {
                float4 hv = h4[j];
                a0 = fmaf(w[4 * j],     hv.x, a0);
                a1 = fmaf(w[4 * j + 1], hv.y, a1);
                a2 = fmaf(w[4 * j + 2], hv.z, a2);
                a3 = fmaf(w[4 * j + 3], hv.w, a3);
            }
            g_sh[tid] = (a0 + a1) + (a2 + a3) + p;
        }
        __syncthreads();
        if (tid < Hh) {
            float si = sigf(g_sh[tid]);
            float sf = sigf(g_sh[tid + 100]);
            float tg = tanh_fast(g_sh[tid + 200]);
            float so = sigf(g_sh[tid + 300]);
            c = sf * c + si * tg;
            float hk = so * tanh_fast(c);
            h_sh[tid] = hk;
            Hout[t * Hh + tid] = hk;
        }
        __syncthreads();
    }
}

// ---------------- K5a: fold scorer weights: u1 = W1^T w, u2 = W2^T w, c0 = b_h2h.w + b_sc ----------------
__global__ void prep_u(const float* __restrict__ Wh2h, const float* __restrict__ bh2h,
                       const float* __restrict__ Wsc, const float* __restrict__ bsc) {
    int k = threadIdx.x;
    if (k < Hh) {
        float u1 = 0.f, u2 = 0.f;
        for (int m = 0; m < Hh; m++) {
            float s = Wsc[m];
            u1 = fmaf(Wh2h[m * 200 + k], s, u1);
            u2 = fmaf(Wh2h[m * 200 + 100 + k], s, u2);
        }
        g_u[k] = u1;
        g_u[100 + k] = u2;
    }
    if (k == 0) {
        float c0 = bsc[0];
        for (int m = 0; m < Hh; m++) c0 = fmaf(bh2h[m], Wsc[m], c0);
        g_u[200] = c0;
    }
}

// ---------------- K5b: EA[i]=exp(h_i.u1), EB[j]=exp(h_j.u2 + c0), S = sum EA (deterministic tree) ----------------
__global__ __launch_bounds__(1024) void score_vec() {
    __shared__ float red[Nn];
    int i = threadIdx.x;
    const float* h = g_H1 + i * Hh;
    float sA = 0.f, sB = 0.f;
    for (int j = 0; j < Hh; j++) {
        float hv = h[j];
        sA = fmaf(hv, g_u[j], sA);
        sB = fmaf(hv, g_u[100 + j], sB);
    }
    float ea = __expf(sA);
    float eb = __expf(sB + g_u[200]);
    g_EA[i] = ea;
    g_EB[i] = eb;
    red[i] = ea;
    __syncthreads();
    for (int s = 512; s > 0; s >>= 1) {
        if (i < s) red[i] += red[i + s];
        __syncthreads();
    }
    if (i == 0) g_S = red[0];
}

// ---------------- K5c: scores[i][j] = EA[i]*EB[j] / (S*EB[j] + eps) ----------------
__global__ void fill_scores(float* __restrict__ out) {
    int i = blockIdx.x;
    float ea = g_EA[i];
    float S = g_S;
    for (int j = threadIdx.x; j < Nn; j += blockDim.x) {
        float eb = g_EB[j];
        out[i * Nn + j] = ea * eb / fmaf(S, eb, EPSV);
    }
}

// ---------------- K5d: labels row softmax over h[1:] @ W_lab^T + b ----------------
__global__ void fill_labels(const float* __restrict__ Wlab, const float* __restrict__ blab,
                            float* __restrict__ out) {
    __shared__ float hsh[Hh];
    __shared__ float esh[Ll];
    int r = blockIdx.x;  // 0..1022
    int tid = threadIdx.x;
    const float* h = g_H1 + (r + 1) * Hh;
    for (int j = tid; j < Hh; j += 64) hsh[j] = h[j];
    __syncthreads();
    if (tid < Ll) {
        float a = blab[tid];
        const float* wr = Wlab + tid * Hh;
        for (int j = 0; j < Hh; j++) a = fmaf(hsh[j], wr[j], a);
        esh[tid] = __expf(a);
    }
    __syncthreads();
    if (tid < Ll) {
        float s = 0.f;
        for (int j = 0; j < Ll; j++) s += esh[j];  // in-order, matches reference sum
        out[Nn * Nn + r * Ll + tid] = esh[tid] / (s + EPSV);
    }
}

// ---------------- launch ----------------
extern "C" void kernel_launch(void* const* d_in, const int* in_sizes, int n_in,
                              void* d_out, int out_size) {
    const int* wi = (const int*)d_in[0];
    const int* ti = (const int*)d_in[1];
    const float* wt = (const float*)d_in[2];
    const float* tt = (const float*)d_in[3];
    const float* Wih0 = (const float*)d_in[4];
    const float* Whh0 = (const float*)d_in[5];
    const float* bih0 = (const float*)d_in[6];
    const float* bhh0 = (const float*)d_in[7];
    const float* Wih1 = (const float*)d_in[8];
    const float* Whh1 = (const float*)d_in[9];
    const float* bih1 = (const float*)d_in[10];
    const float* bhh1 = (const float*)d_in[11];
    const float* Wh2h = (const float*)d_in[12];
    const float* bh2h = (const float*)d_in[13];
    const float* Wsc = (const float*)d_in[14];
    const float* bsc = (const float*)d_in[15];
    const float* Wlab = (const float*)d_in[16];
    const float* blab = (const float*)d_in[17];
    float* out = (float*)d_out;

    float *pE, *pP, *pH0, *pH1;
    cudaGetSymbolAddress((void**)&pE, g_E);
    cudaGetSymbolAddress((void**)&pP, g_P);
    cudaGetSymbolAddress((void**)&pH0, g_H0);
    cudaGetSymbolAddress((void**)&pH1, g_H1);

    dim3 gg(13, 16);  // 13*32 >= 400 cols, 16*64 = 1024 rows

    gather_emb<<<Nn, 128>>>(wi, ti, wt, tt);
    gemm_bias<<<gg, 256>>>(pE, Wih0, bih0, bhh0, pP, KE);
    lstm_rec<<<1, 512>>>(Whh0, pP, pH0);
    gemm_bias<<<gg, 256>>>(pH0, Wih1, bih1, bhh1, pP, Hh);
    lstm_rec<<<1, 512>>>(Whh1, pP, pH1);
    prep_u<<<1, 128>>>(Wh2h, bh2h, Wsc, bsc);
    score_vec<<<1, 1024>>>();
    fill_scores<<<Nn, 256>>>(out);
    fill_labels<<<Nn - 1, 64>>>(Wlab, blab, out);
}

// round 2
// speedup vs baseline: 1.4208x; 1.4208x over previous
#include <cuda_runtime.h>

#define Nn 1024
#define Hh 100
#define Gg 400
#define KE 125
#define Ll 40
#define EPSV 1e-20f

// ---------------- scratch (device globals; no allocation allowed) ----------------
__device__ float g_E[Nn * KE];     // embeddings [1024,125]
__device__ float g_P[Nn * Gg];     // precomputed input-projection gates [1024,400] (reused per layer)
__device__ float g_H0[Nn * Hh];    // layer0 hidden states
__device__ float g_H1[Nn * Hh];    // layer1 hidden states
__device__ float g_u[2 * Hh + 1];  // u1[100], u2[100], c0
__device__ float g_EA[Nn];
__device__ float g_EB[Nn];
__device__ float g_S;

// ---------------- helpers ----------------
__device__ __forceinline__ float sigf(float x) {
    // 1/(1+e^-x) with fast reciprocal (MUFU.RCP) instead of IEEE div
    float e = __expf(-x);
    return __fdividef(1.f, 1.f + e);
}
__device__ __forceinline__ float tanh_fast(float x) {
    x = fminf(fmaxf(x, -15.f), 15.f);
    float e = __expf(2.f * x);
    return __fdividef(e - 1.f, e + 1.f);
}

#define FMA2(acc, a, b) asm("fma.rn.f32x2 %0, %1, %2, %0;" : "+l"(acc) : "l"(a), "l"(b))
__device__ __forceinline__ float unpack_sum(unsigned long long v) {
    float lo, hi;
    asm("mov.b64 {%0, %1}, %2;" : "=f"(lo), "=f"(hi) : "l"(v));
    return lo + hi;
}

// ---------------- K0: embedding gather ----------------
__global__ void gather_emb(const int* __restrict__ wi, const int* __restrict__ ti,
                           const float* __restrict__ wt, const float* __restrict__ tt) {
    int t = blockIdx.x;
    int w = wi[t];
    int g = ti[t];
    for (int j = threadIdx.x; j < KE; j += blockDim.x)
        g_E[t * KE + j] = (j < 100) ? wt[w * 100 + j] : tt[g * 25 + (j - 100)];
}

// ---------------- K1/K3: C[1024,400] = X[1024,K] @ W[400,K]^T + b1 + b2 ----------------
__global__ __launch_bounds__(256) void gemm_bias(const float* __restrict__ X,
                                                 const float* __restrict__ W,
                                                 const float* __restrict__ b1,
                                                 const float* __restrict__ b2,
                                                 float* __restrict__ C, int K) {
    __shared__ float Xs[64 * 127];  // rows of X tile, padded stride 127 (odd)
    __shared__ float Ws[32 * 127];  // rows of W tile
    int m0 = blockIdx.y * 64;
    int n0 = blockIdx.x * 32;
    int tid = threadIdx.x;

    for (int idx = tid; idx < 64 * K; idx += 256) {
        int r = idx / K, c = idx - r * K;
        Xs[r * 127 + c] = X[(m0 + r) * K + c];  // M=1024 divisible by 64, no guard
    }
    for (int idx = tid; idx < 32 * K; idx += 256) {
        int r = idx / K, c = idx - r * K;
        int n = n0 + r;
        Ws[r * 127 + c] = (n < Gg) ? W[n * K + c] : 0.f;
    }
    __syncthreads();

    int ty = tid >> 5, tx = tid & 31;
    float acc[8] = {0, 0, 0, 0, 0, 0, 0, 0};
    for (int k = 0; k < K; k++) {
        float wv = Ws[tx * 127 + k];  // stride 127: conflict-free
#pragma unroll
        for (int r = 0; r < 8; r++)
            acc[r] = fmaf(Xs[(ty + 8 * r) * 127 + k], wv, acc[r]);  // broadcast
    }
    int n = n0 + tx;
    if (n < Gg) {
        float bb = b1[n] + b2[n];
#pragma unroll
        for (int r = 0; r < 8; r++)
            C[(m0 + ty + 8 * r) * Gg + n] = acc[r] + bb;
    }
}

// ---------------- K2/K4: sequential LSTM recurrence (single CTA) ----------------
// P already contains x_t @ W_ih^T + b_ih + b_hh. Only h @ W_hh^T is on the chain.
// 416 threads (NOT 512): reg cap = 65536/416 = 157/thread, so the 100-reg packed
// weight array stays in registers (512 capped at 128 -> spills -> the R1 3x slowdown).
__global__ __launch_bounds__(416, 1) void lstm_rec(const float* __restrict__ Whh,
                                                   const float* __restrict__ P,
                                                   float* __restrict__ Hout) {
    __shared__ __align__(16) float h_sh[Hh];
    __shared__ float g_sh[Gg];
    int tid = threadIdx.x;

    // 100 weights per thread, packed as 50 x f32x2 (100 regs)
    unsigned long long w2[50];
    if (tid < Gg) {
        const ulonglong2* Wr = reinterpret_cast<const ulonglong2*>(Whh + tid * Hh);  // rows are 400B: 16B aligned
#pragma unroll
        for (int j = 0; j < 25; j++) {
            ulonglong2 v = Wr[j];
            w2[2 * j] = v.x;
            w2[2 * j + 1] = v.y;
        }
    }
    float c = 0.f;
    if (tid < Hh) h_sh[tid] = 0.f;
    __syncthreads();

    float p = (tid < Gg) ? P[tid] : 0.f;  // P row for t=0
    for (int t = 0; t < Nn; t++) {
        // prefetch next step's P row immediately (hidden behind dot+act+barriers)
        float pn = 0.f;
        if (tid < Gg && t + 1 < Nn) pn = P[(t + 1) * Gg + tid];

        if (tid < Gg) {
            const ulonglong2* h2 = reinterpret_cast<const ulonglong2*>(h_sh);
            unsigned long long a0 = 0ull, a1 = 0ull, a2 = 0ull, a3 = 0ull;
#pragma unroll
            for (int j = 0; j < 25; j++) {
                ulonglong2 hv = h2[j];  // LDS.128 broadcast (all lanes same addr)
                if (j & 1) {
                    FMA2(a2, w2[2 * j], hv.x);
                    FMA2(a3, w2[2 * j + 1], hv.y);
                } else {
                    FMA2(a0, w2[2 * j], hv.x);
                    FMA2(a1, w2[2 * j + 1], hv.y);
                }
            }
            g_sh[tid] = (unpack_sum(a0) + unpack_sum(a1)) + (unpack_sum(a2) + unpack_sum(a3)) + p;
        }
        __syncthreads();
        if (tid < Hh) {
            float si = sigf(g_sh[tid]);
            float sf = sigf(g_sh[tid + 100]);
            float tg = tanh_fast(g_sh[tid + 200]);
            float so = sigf(g_sh[tid + 300]);
            c = sf * c + si * tg;
            float hk = so * tanh_fast(c);
            h_sh[tid] = hk;
            Hout[t * Hh + tid] = hk;
        }
        __syncthreads();
        p = pn;
    }
}

// ---------------- K5a: fold scorer weights: u1 = W1^T w, u2 = W2^T w, c0 = b_h2h.w + b_sc ----------------
__global__ void prep_u(const float* __restrict__ Wh2h, const float* __restrict__ bh2h,
                       const float* __restrict__ Wsc, const float* __restrict__ bsc) {
    int k = threadIdx.x;
    if (k < Hh) {
        float u1 = 0.f, u2 = 0.f;
        for (int m = 0; m < Hh; m++) {
            float s = Wsc[m];
            u1 = fmaf(Wh2h[m * 200 + k], s, u1);
            u2 = fmaf(Wh2h[m * 200 + 100 + k], s, u2);
        }
        g_u[k] = u1;
        g_u[100 + k] = u2;
    }
    if (k == 0) {
        float c0 = bsc[0];
        for (int m = 0; m < Hh; m++) c0 = fmaf(bh2h[m], Wsc[m], c0);
        g_u[200] = c0;
    }
}

// ---------------- K5b: EA[i]=exp(h_i.u1), EB[j]=exp(h_j.u2 + c0), S = sum EA (deterministic tree) ----------------
__global__ __launch_bounds__(1024) void score_vec() {
    __shared__ float red[Nn];
    int i = threadIdx.x;
    const float* h = g_H1 + i * Hh;
    float sA = 0.f, sB = 0.f;
    for (int j = 0; j < Hh; j++) {
        float hv = h[j];
        sA = fmaf(hv, g_u[j], sA);
        sB = fmaf(hv, g_u[100 + j], sB);
    }
    float ea = __expf(sA);
    float eb = __expf(sB + g_u[200]);
    g_EA[i] = ea;
    g_EB[i] = eb;
    red[i] = ea;
    __syncthreads();
    for (int s = 512; s > 0; s >>= 1) {
        if (i < s) red[i] += red[i + s];
        __syncthreads();
    }
    if (i == 0) g_S = red[0];
}

// ---------------- K5c: scores[i][j] = EA[i]*EB[j] / (S*EB[j] + eps) ----------------
__global__ void fill_scores(float* __restrict__ out) {
    int i = blockIdx.x;
    float ea = g_EA[i];
    float S = g_S;
    for (int j = threadIdx.x; j < Nn; j += blockDim.x) {
        float eb = g_EB[j];
        out[i * Nn + j] = __fdividef(ea * eb, fmaf(S, eb, EPSV));
    }
}

// ---------------- K5d: labels row softmax over h[1:] @ W_lab^T + b ----------------
__global__ void fill_labels(const float* __restrict__ Wlab, const float* __restrict__ blab,
                            float* __restrict__ out) {
    __shared__ float hsh[Hh];
    __shared__ float esh[Ll];
    int r = blockIdx.x;  // 0..1022
    int tid = threadIdx.x;
    const float* h = g_H1 + (r + 1) * Hh;
    for (int j = tid; j < Hh; j += 64) hsh[j] = h[j];
    __syncthreads();
    if (tid < Ll) {
        float a = blab[tid];
        const float* wr = Wlab + tid * Hh;
        for (int j = 0; j < Hh; j++) a = fmaf(hsh[j], wr[j], a);
        esh[tid] = __expf(a);
    }
    __syncthreads();
    if (tid < Ll) {
        float s = 0.f;
        for (int j = 0; j < Ll; j++) s += esh[j];  // in-order, matches reference sum
        out[Nn * Nn + r * Ll + tid] = __fdividef(esh[tid], s + EPSV);
    }
}

// ---------------- launch ----------------
extern "C" void kernel_launch(void* const* d_in, const int* in_sizes, int n_in,
                              void* d_out, int out_size) {
    const int* wi = (const int*)d_in[0];
    const int* ti = (const int*)d_in[1];
    const float* wt = (const float*)d_in[2];
    const float* tt = (const float*)d_in[3];
    const float* Wih0 = (const float*)d_in[4];
    const float* Whh0 = (const float*)d_in[5];
    const float* bih0 = (const float*)d_in[6];
    const float* bhh0 = (const float*)d_in[7];
    const float* Wih1 = (const float*)d_in[8];
    const float* Whh1 = (const float*)d_in[9];
    const float* bih1 = (const float*)d_in[10];
    const float* bhh1 = (const float*)d_in[11];
    const float* Wh2h = (const float*)d_in[12];
    const float* bh2h = (const float*)d_in[13];
    const float* Wsc = (const float*)d_in[14];
    const float* bsc = (const float*)d_in[15];
    const float* Wlab = (const float*)d_in[16];
    const float* blab = (const float*)d_in[17];
    float* out = (float*)d_out;

    float *pE, *pP, *pH0, *pH1;
    cudaGetSymbolAddress((void**)&pE, g_E);
    cudaGetSymbolAddress((void**)&pP, g_P);
    cudaGetSymbolAddress((void**)&pH0, g_H0);
    cudaGetSymbolAddress((void**)&pH1, g_H1);

    dim3 gg(13, 16);  // 13*32 >= 400 cols, 16*64 = 1024 rows

    gather_emb<<<Nn, 128>>>(wi, ti, wt, tt);
    gemm_bias<<<gg, 256>>>(pE, Wih0, bih0, bhh0, pP, KE);
    lstm_rec<<<1, 416>>>(Whh0, pP, pH0);
    gemm_bias<<<gg, 256>>>(pH0, Wih1, bih1, bhh1, pP, Hh);
    lstm_rec<<<1, 416>>>(Whh1, pP, pH1);
    prep_u<<<1, 128>>>(Wh2h, bh2h, Wsc, bsc);
    score_vec<<<1, 1024>>>();
    fill_scores<<<Nn, 256>>>(out);
    fill_labels<<<Nn - 1, 64>>>(Wlab, blab, out);
}